// round 14
// baseline (speedup 1.0000x reference)
#include <cuda_runtime.h>
#include <math.h>
#include <stdint.h>

#define S_LEN 2048
#define B_SZ  64
#define E_SZ  256
#define H_SZ  256
#define NSCAN 32          // scan CTAs, 2 batch rows each
#define NWORK 116         // producer CTAs (32 + 116 = 148 = full chip)

// Scratch for x_proj: [S, B, H] fp32 = 134 MB
__device__ float g_xproj[(size_t)S_LEN * B_SZ * H_SZ];
// Per-step completion flags (zeroed each call)
__device__ int g_flag[S_LEN];

typedef unsigned long long ull;

// ---- packed f32x2 helpers ---------------------------------------------------
__device__ __forceinline__ ull fma2(ull a, ull b, ull c) {
    ull d;
    asm("fma.rn.f32x2 %0, %1, %2, %3;" : "=l"(d) : "l"(a), "l"(b), "l"(c));
    return d;
}
__device__ __forceinline__ ull add2(ull a, ull b) {
    ull d;
    asm("add.rn.f32x2 %0, %1, %2;" : "=l"(d) : "l"(a), "l"(b));
    return d;
}
__device__ __forceinline__ ull pack2(float lo, float hi) {
    ull d;
    asm("mov.b64 %0, {%1, %2};" : "=l"(d) : "f"(lo), "f"(hi));
    return d;
}
__device__ __forceinline__ void unpack2(ull v, float& lo, float& hi) {
    asm("mov.b64 {%0, %1}, %2;" : "=f"(lo), "=f"(hi) : "l"(v));
}

// fast tanh: tanh(x) = 1 - 2/(exp(2x)+1), via MUFU.EX2 + MUFU.RCP (~1e-6 err)
__device__ __forceinline__ float fast_tanh(float x) {
    float u, r;
    asm("ex2.approx.f32 %0, %1;" : "=f"(u) : "f"(x * 2.885390082f));
    asm("rcp.approx.f32 %0, %1;" : "=f"(r) : "f"(u + 1.0f));
    return fmaf(-2.0f, r, 1.0f);
}

// ---- release/acquire flag ops ----------------------------------------------
__device__ __forceinline__ int ld_acquire(const int* p) {
    int v;
    asm volatile("ld.acquire.gpu.global.b32 %0, [%1];" : "=r"(v) : "l"(p) : "memory");
    return v;
}
__device__ __forceinline__ void st_release(int* p, int v) {
    asm volatile("st.release.gpu.global.b32 [%0], %1;" :: "l"(p), "r"(v) : "memory");
}

__global__ void zero_flags() {
    const int i = blockIdx.x * blockDim.x + threadIdx.x;
    if (i < S_LEN) g_flag[i] = 0;
}

// ---------------------------------------------------------------------------
// Fused kernel, grid 148 x 512 (one wave):
//   blockIdx <  32 : SCAN CTA — TWO batch rows (2*blockIdx, +1), interleaved.
//                    W registers/SMEM shared across both rows; both rows'
//                    FMA phases back-to-back (independent chains -> latency
//                    overlap), ONE barrier pair per step for both rows,
//                    reduce phase uses all 256 reducer threads (row = t>>7).
//   blockIdx >= 32 : WORKER CTA (R12 v2 producer), steps s = w, w+116, ...
// Sync: ONE ld.acquire per step by t0 (probe at top, confirm before BAR(A));
// reducers use plain LDG for x (hb chain: release->acquire->BAR).
// ---------------------------------------------------------------------------
#define K_REG  18
#define K_SMEM 14

__global__ __launch_bounds__(512, 1) void fused_kernel(
    const float* __restrict__ sent,   // [S*B, 256]
    const float* __restrict__ Wih,    // [256,256]
    const float* __restrict__ bias,   // [256]
    const float* __restrict__ Whh,    // [256,256]
    const float* __restrict__ h0,     // [64,256]
    float* __restrict__ out)          // [64,256]
{
    extern __shared__ ull smem[];
    const int t = threadIdx.x;

    if (blockIdx.x < NSCAN) {
        // =================== SCAN: 2 rows per CTA ==========================
        // layout (ull units): sW 8*14*64 u2 = 14336 ull (112 KB)
        //                     part 2 rows * 1024 ull   (16 KB)
        //                     hbuf 2 rows * 256 ull    (4 KB)
        ulonglong2* sW   = (ulonglong2*)smem;
        ull*        part = smem + (size_t)8 * K_SMEM * 64 * 2;   // [2][8][128]
        ull*        hbuf = part + 2 * 1024;                      // [2][256]

        const int b0 = blockIdx.x * 2;
        const int ks = t >> 6;
        const int jq = t & 63;
        const int kbase = ks * 32;

        // register W slice (18 k's x 4 cols) — shared by both rows
        ull wr[2 * K_REG];
        #pragma unroll
        for (int i = 0; i < K_REG; i++) {
            const int k = kbase + i;
            const ulonglong2 wv = *(const ulonglong2*)&Whh[(size_t)k * 256 + 4 * jq];
            wr[2 * i]     = wv.x;
            wr[2 * i + 1] = wv.y;
        }

        // SMEM W slice (14 k's per ks-group)
        for (int idx = t; idx < 8 * K_SMEM * 64; idx += 512) {
            const int fjq = idx & 63;
            const int fm  = (idx >> 6) % K_SMEM;
            const int fks = idx / (K_SMEM * 64);
            const int k   = fks * 32 + K_REG + fm;
            sW[(fks * K_SMEM + fm) * 64 + fjq] =
                *(const ulonglong2*)&Whh[(size_t)k * 256 + 4 * fjq];
        }

        // init h for both rows (replicated pairs)
        if (t < 256) {
            const float hA = h0[(size_t)b0 * 256 + t];
            const float hB = h0[(size_t)(b0 + 1) * 256 + t];
            hbuf[t]       = pack2(hA, hA);
            hbuf[256 + t] = pack2(hB, hB);
        }

        // prologue: t0 waits for step 0's flag; BAR publishes ordering
        if (t == 0) {
            while (ld_acquire(&g_flag[0]) == 0) __nanosleep(64);
        }
        __syncthreads();

        // x state: reducer thread t<256 owns (row r = t>>7, col-pair p = t&127)
        const int rrow = t >> 7;           // 0 or 1 (valid for t<256)
        const int rp   = t & 127;
        ull xcur = 0;
        if (t < 256)
            xcur = *(const ull*)
                &g_xproj[((size_t)0 * B_SZ + b0 + rrow) * 256 + 2 * rp];

        const ull* hbA = hbuf + kbase;
        const ull* hbB = hbuf + 256 + kbase;

        for (int s = 0; s < S_LEN; s++) {
            int fv = 1;
            if (t == 0 && s + 1 < S_LEN) fv = ld_acquire(&g_flag[s + 1]);

            ull aA0 = 0, aA1 = 0, aB0 = 0, aB1 = 0;

            // register half: k = kbase + 0 .. kbase + 17 (W shared, 2 rows)
            #pragma unroll
            for (int p = 0; p < K_REG / 2; p++) {
                const ulonglong2 hvA = *(const ulonglong2*)(hbA + 2 * p);
                const ulonglong2 hvB = *(const ulonglong2*)(hbB + 2 * p);
                aA0 = fma2(wr[4 * p + 0], hvA.x, aA0);
                aA1 = fma2(wr[4 * p + 1], hvA.x, aA1);
                aB0 = fma2(wr[4 * p + 0], hvB.x, aB0);
                aB1 = fma2(wr[4 * p + 1], hvB.x, aB1);
                aA0 = fma2(wr[4 * p + 2], hvA.y, aA0);
                aA1 = fma2(wr[4 * p + 3], hvA.y, aA1);
                aB0 = fma2(wr[4 * p + 2], hvB.y, aB0);
                aB1 = fma2(wr[4 * p + 3], hvB.y, aB1);
            }
            // smem half: k = kbase + 18 .. kbase + 31 (one sW read, 2 rows)
            #pragma unroll
            for (int m = 0; m < K_SMEM; m += 2) {
                const ulonglong2 hvA = *(const ulonglong2*)(hbA + K_REG + m);
                const ulonglong2 hvB = *(const ulonglong2*)(hbB + K_REG + m);
                const ulonglong2 w0 = sW[(ks * K_SMEM + m) * 64 + jq];
                const ulonglong2 w1 = sW[(ks * K_SMEM + m + 1) * 64 + jq];
                aA0 = fma2(w0.x, hvA.x, aA0);
                aA1 = fma2(w0.y, hvA.x, aA1);
                aB0 = fma2(w0.x, hvB.x, aB0);
                aB1 = fma2(w0.y, hvB.x, aB1);
                aA0 = fma2(w1.x, hvA.y, aA0);
                aA1 = fma2(w1.y, hvA.y, aA1);
                aB0 = fma2(w1.x, hvB.y, aB0);
                aB1 = fma2(w1.y, hvB.y, aB1);
            }

            part[ks * 128 + 2 * jq]            = aA0;
            part[ks * 128 + 2 * jq + 1]        = aA1;
            part[1024 + ks * 128 + 2 * jq]     = aB0;
            part[1024 + ks * 128 + 2 * jq + 1] = aB1;

            if (t == 0 && s + 1 < S_LEN) {
                while (fv == 0) {
                    __nanosleep(32);
                    fv = ld_acquire(&g_flag[s + 1]);
                }
            }
            __syncthreads();   // (A) partials visible; x[s+1] ordering done

            if (t < 256) {
                const ull* pr = part + rrow * 1024;
                ull v = add2(add2(add2(pr[0 * 128 + rp], pr[1 * 128 + rp]),
                                  add2(pr[2 * 128 + rp], pr[3 * 128 + rp])),
                             add2(add2(pr[4 * 128 + rp], pr[5 * 128 + rp]),
                                  add2(pr[6 * 128 + rp], pr[7 * 128 + rp])));
                v = add2(v, xcur);
                float vx, vy;
                unpack2(v, vx, vy);
                const float tx = fast_tanh(vx);
                const float ty = fast_tanh(vy);
                hbuf[rrow * 256 + 2 * rp]     = pack2(tx, tx);
                hbuf[rrow * 256 + 2 * rp + 1] = pack2(ty, ty);

                if (s + 1 < S_LEN)
                    xcur = *(const ull*)
                        &g_xproj[((size_t)(s + 1) * B_SZ + b0 + rrow) * 256 + 2 * rp];
            }
            __syncthreads();   // (B) new h visible
        }

        if (t < 256) {
            float vx, vy, wx, wy;
            unpack2(hbuf[rrow * 256 + 2 * rp],     vx, vy);
            unpack2(hbuf[rrow * 256 + 2 * rp + 1], wx, wy);
            out[(size_t)(b0 + rrow) * 256 + 2 * rp]     = vx;
            out[(size_t)(b0 + rrow) * 256 + 2 * rp + 1] = wx;
        }
    } else {
        // =================== WORKER (R12 v2) ===============================
        float* xs = (float*)smem;
        ull*   Wc = (ull*)((char*)smem + 64 * 1024);

        const int w  = blockIdx.x - NSCAN;
        const int jq = t & 63;
        const int rg = t >> 6;

        const ull b01 = *(const ull*)&bias[4 * jq];
        const ull b23 = *(const ull*)&bias[4 * jq + 2];

        for (int s = w; s < S_LEN; s += NWORK) {
            {
                const float4* src = (const float4*)(sent + (size_t)s * 64 * 256);
                #pragma unroll
                for (int i = 0; i < 8; i++)
                    ((float4*)xs)[t + i * 512] = src[t + i * 512];
            }
            __syncthreads();

            ull acc0[8], acc1[8];
            #pragma unroll
            for (int r = 0; r < 8; r++) { acc0[r] = b01; acc1[r] = b23; }

            for (int c = 0; c < 8; c++) {
                if (c) __syncthreads();
                #pragma unroll
                for (int i = 0; i < 8; i++) {
                    const int idx = t + i * 512;
                    const int ik  = idx >> 7;
                    const int p   = idx & 127;
                    Wc[idx] = *(const ull*)&Wih[(size_t)(c * 32 + ik) * 256 + 2 * p];
                }
                __syncthreads();

                #pragma unroll
                for (int q = 0; q < 8; q++) {
                    float4 xv[8];
                    #pragma unroll
                    for (int r = 0; r < 8; r++)
                        xv[r] = *(const float4*)
                            &xs[(rg * 8 + r) * 256 + c * 32 + q * 4];
                    #pragma unroll
                    for (int e = 0; e < 4; e++) {
                        const ulonglong2 wv =
                            *(const ulonglong2*)&Wc[(q * 4 + e) * 128 + 2 * jq];
                        #pragma unroll
                        for (int r = 0; r < 8; r++) {
                            const float xe = (e == 0) ? xv[r].x :
                                             (e == 1) ? xv[r].y :
                                             (e == 2) ? xv[r].z : xv[r].w;
                            const ull xp = pack2(xe, xe);
                            acc0[r] = fma2(wv.x, xp, acc0[r]);
                            acc1[r] = fma2(wv.y, xp, acc1[r]);
                        }
                    }
                }
            }

            #pragma unroll
            for (int r = 0; r < 8; r++) {
                ull* dst = (ull*)&g_xproj[((size_t)s * 64 + rg * 8 + r) * 256 + 4 * jq];
                dst[0] = acc0[r];
                dst[1] = acc1[r];
            }
            __threadfence();
            __syncthreads();
            if (t == 0) st_release(&g_flag[s], 1);
        }
    }
}

// ---------------------------------------------------------------------------
extern "C" void kernel_launch(void* const* d_in, const int* in_sizes, int n_in,
                              void* d_out, int out_size)
{
    const float* sentence = (const float*)d_in[0];
    const float* h0       = (const float*)d_in[1];
    const float* W_ih     = (const float*)d_in[2];
    const float* W_hh     = (const float*)d_in[3];
    const float* bias     = (const float*)d_in[4];
    float* out = (float*)d_out;

    (void)in_sizes; (void)n_in; (void)out_size;

    zero_flags<<<(S_LEN + 511) / 512, 512>>>();

    // smem: sW 112KB + part 16KB + hbuf 4KB = 132 KB (worker needs 96 KB)
    const int smem_bytes = (8 * K_SMEM * 64) * 16 + 2 * 1024 * 8 + 2 * 256 * 8;
    cudaFuncSetAttribute(fused_kernel,
                         cudaFuncAttributeMaxDynamicSharedMemorySize,
                         smem_bytes);
    fused_kernel<<<NSCAN + NWORK, 512, smem_bytes>>>(
        sentence, W_ih, bias, W_hh, h0, out);
}

// round 15
// speedup vs baseline: 1.3853x; 1.3853x over previous
#include <cuda_runtime.h>
#include <math.h>
#include <stdint.h>

#define S_LEN 2048
#define B_SZ  64
#define E_SZ  256
#define H_SZ  256
#define NWORK 84          // producer CTAs (64 + 84 = 148 = full chip)

// Scratch for x_proj: [S, B, H] fp32 = 134 MB
__device__ float g_xproj[(size_t)S_LEN * B_SZ * H_SZ];
// Per-step completion flags (zeroed each call)
__device__ int g_flag[S_LEN];

typedef unsigned long long ull;

// ---- packed f32x2 helpers ---------------------------------------------------
__device__ __forceinline__ ull fma2(ull a, ull b, ull c) {
    ull d;
    asm("fma.rn.f32x2 %0, %1, %2, %3;" : "=l"(d) : "l"(a), "l"(b), "l"(c));
    return d;
}
__device__ __forceinline__ ull pack2(float lo, float hi) {
    ull d;
    asm("mov.b64 %0, {%1, %2};" : "=l"(d) : "f"(lo), "f"(hi));
    return d;
}
__device__ __forceinline__ void unpack2(ull v, float& lo, float& hi) {
    asm("mov.b64 {%0, %1}, %2;" : "=f"(lo), "=f"(hi) : "l"(v));
}

// fast tanh: tanh(x) = 1 - 2/(exp(2x)+1), via MUFU.EX2 + MUFU.RCP (~1e-6 err)
__device__ __forceinline__ float fast_tanh(float x) {
    float u, r;
    asm("ex2.approx.f32 %0, %1;" : "=f"(u) : "f"(x * 2.885390082f));
    asm("rcp.approx.f32 %0, %1;" : "=f"(r) : "f"(u + 1.0f));
    return fmaf(-2.0f, r, 1.0f);
}

// ---- release/acquire flag ops ----------------------------------------------
__device__ __forceinline__ int ld_acquire(const int* p) {
    int v;
    asm volatile("ld.acquire.gpu.global.b32 %0, [%1];" : "=r"(v) : "l"(p) : "memory");
    return v;
}
__device__ __forceinline__ void st_release(int* p, int v) {
    asm volatile("st.release.gpu.global.b32 [%0], %1;" :: "l"(p), "r"(v) : "memory");
}

__global__ void zero_flags() {
    const int i = blockIdx.x * blockDim.x + threadIdx.x;
    if (i < S_LEN) g_flag[i] = 0;
}

// ---------------------------------------------------------------------------
// Fused kernel, grid 148 x 512 (one wave):
//   blockIdx <  64 : SCAN CTA (R13 structure + 2 micro-opts:
//                    (1) SMEM-W half of the dot issued BEFORE register half
//                        so LDS latency is covered by register FMAs;
//                    (2) reduce phase = 256 threads, one scalar column each)
//   blockIdx >= 64 : WORKER CTA (R12 v2: W_ih staged via SMEM, f32x2 FMAs)
// Sync: ONE ld.acquire per step by t0 (probe at top, confirm before BAR(A));
// consumers use plain LDG for x (hb chain: release -> acquire -> BAR).
// ---------------------------------------------------------------------------
#define K_REG  20
#define K_SMEM 12

__global__ __launch_bounds__(512, 1) void fused_kernel(
    const float* __restrict__ sent,   // [S*B, 256]
    const float* __restrict__ Wih,    // [256,256]
    const float* __restrict__ bias,   // [256]
    const float* __restrict__ Whh,    // [256,256]
    const float* __restrict__ h0,     // [64,256]
    float* __restrict__ out)          // [64,256]
{
    extern __shared__ ull smem[];
    const int t = threadIdx.x;

    if (blockIdx.x < B_SZ) {
        // =================== SCAN ==========================================
        ulonglong2* sW     = (ulonglong2*)smem;
        ull*        part   = (ull*)(smem + 8 * 12 * 64 * 2);
        ull*        hbuf   = part + 8 * 128;
        float*      part_f = (float*)part;       // scalar view [8][256]

        const int b  = blockIdx.x;
        const int ks = t >> 6;
        const int jq = t & 63;
        const int kbase = ks * 32;

        ull wr[2 * K_REG];
        #pragma unroll
        for (int i = 0; i < K_REG; i++) {
            const int k = kbase + i;
            const ulonglong2 wv = *(const ulonglong2*)&Whh[(size_t)k * 256 + 4 * jq];
            wr[2 * i]     = wv.x;
            wr[2 * i + 1] = wv.y;
        }

        for (int idx = t; idx < 8 * K_SMEM * 64; idx += 512) {
            const int fjq = idx & 63;
            const int fm  = (idx >> 6) % K_SMEM;
            const int fks = idx / (K_SMEM * 64);
            const int k   = fks * 32 + K_REG + fm;
            sW[(fks * K_SMEM + fm) * 64 + fjq] =
                *(const ulonglong2*)&Whh[(size_t)k * 256 + 4 * fjq];
        }

        if (t < 256) {
            const float h = h0[(size_t)b * 256 + t];
            hbuf[t] = pack2(h, h);
        }

        // prologue: t0 waits for step 0's flag; BAR publishes ordering
        if (t == 0) {
            while (ld_acquire(&g_flag[0]) == 0) __nanosleep(64);
        }
        __syncthreads();

        // x state: thread t < 256 owns scalar column t
        float xcur = 0.f, hlast = 0.f;
        if (t < 256)
            xcur = g_xproj[((size_t)0 * B_SZ + b) * 256 + t];

        const ull* hb = hbuf + kbase;

        for (int s = 0; s < S_LEN; s++) {
            // t0: non-blocking probe of flag[s+1] (latency hidden by FMAs)
            int fv = 1;
            if (t == 0 && s + 1 < S_LEN) fv = ld_acquire(&g_flag[s + 1]);

            ull a01 = 0, a23 = 0;

            // ---- SMEM half FIRST: k = kbase+20 .. kbase+31 ----
            // (issues all 12 LDS.128 up front; register-half FMAs below
            //  cover their latency)
            #pragma unroll
            for (int m = 0; m < K_SMEM; m += 2) {
                const ulonglong2 hv = *(const ulonglong2*)(hb + K_REG + m);
                const ulonglong2 w0 = sW[(ks * K_SMEM + m) * 64 + jq];
                const ulonglong2 w1 = sW[(ks * K_SMEM + m + 1) * 64 + jq];
                a01 = fma2(w0.x, hv.x, a01);
                a23 = fma2(w0.y, hv.x, a23);
                a01 = fma2(w1.x, hv.y, a01);
                a23 = fma2(w1.y, hv.y, a23);
            }
            // ---- register half: k = kbase+0 .. kbase+19 ----
            #pragma unroll
            for (int p = 0; p < K_REG / 2; p++) {
                const ulonglong2 hv = *(const ulonglong2*)(hb + 2 * p);
                a01 = fma2(wr[4 * p + 0], hv.x, a01);
                a23 = fma2(wr[4 * p + 1], hv.x, a23);
                a01 = fma2(wr[4 * p + 2], hv.y, a01);
                a23 = fma2(wr[4 * p + 3], hv.y, a23);
            }

            part[ks * 128 + 2 * jq]     = a01;
            part[ks * 128 + 2 * jq + 1] = a23;

            // t0: confirm flag[s+1] before BAR(A) (poll only if behind)
            if (t == 0 && s + 1 < S_LEN) {
                while (fv == 0) {
                    __nanosleep(32);
                    fv = ld_acquire(&g_flag[s + 1]);
                }
            }
            __syncthreads();   // (A) partials visible; x[s+1] ordering done

            // ---- reduce: 256 threads, one scalar column each ----
            if (t < 256) {
                const float v0 = part_f[0 * 256 + t] + part_f[1 * 256 + t];
                const float v1 = part_f[2 * 256 + t] + part_f[3 * 256 + t];
                const float v2 = part_f[4 * 256 + t] + part_f[5 * 256 + t];
                const float v3 = part_f[6 * 256 + t] + part_f[7 * 256 + t];
                const float v  = ((v0 + v1) + (v2 + v3)) + xcur;
                const float h  = fast_tanh(v);
                hlast = h;
                hbuf[t] = pack2(h, h);

                // plain LDG prefetch of x[s+1] (consumed next step)
                if (s + 1 < S_LEN)
                    xcur = g_xproj[((size_t)(s + 1) * B_SZ + b) * 256 + t];
            }
            __syncthreads();   // (B) new h visible
        }

        if (t < 256)
            out[(size_t)b * 256 + t] = hlast;
    } else {
        // =================== WORKER (R12 v2) ===============================
        float* xs = (float*)smem;
        ull*   Wc = (ull*)((char*)smem + 64 * 1024);

        const int w  = blockIdx.x - B_SZ;
        const int jq = t & 63;
        const int rg = t >> 6;

        const ull b01 = *(const ull*)&bias[4 * jq];
        const ull b23 = *(const ull*)&bias[4 * jq + 2];

        for (int s = w; s < S_LEN; s += NWORK) {
            {
                const float4* src = (const float4*)(sent + (size_t)s * 64 * 256);
                #pragma unroll
                for (int i = 0; i < 8; i++)
                    ((float4*)xs)[t + i * 512] = src[t + i * 512];
            }
            __syncthreads();

            ull acc0[8], acc1[8];
            #pragma unroll
            for (int r = 0; r < 8; r++) { acc0[r] = b01; acc1[r] = b23; }

            for (int c = 0; c < 8; c++) {
                if (c) __syncthreads();
                #pragma unroll
                for (int i = 0; i < 8; i++) {
                    const int idx = t + i * 512;
                    const int ik  = idx >> 7;
                    const int p   = idx & 127;
                    Wc[idx] = *(const ull*)&Wih[(size_t)(c * 32 + ik) * 256 + 2 * p];
                }
                __syncthreads();

                #pragma unroll
                for (int q = 0; q < 8; q++) {
                    float4 xv[8];
                    #pragma unroll
                    for (int r = 0; r < 8; r++)
                        xv[r] = *(const float4*)
                            &xs[(rg * 8 + r) * 256 + c * 32 + q * 4];
                    #pragma unroll
                    for (int e = 0; e < 4; e++) {
                        const ulonglong2 wv =
                            *(const ulonglong2*)&Wc[(q * 4 + e) * 128 + 2 * jq];
                        #pragma unroll
                        for (int r = 0; r < 8; r++) {
                            const float xe = (e == 0) ? xv[r].x :
                                             (e == 1) ? xv[r].y :
                                             (e == 2) ? xv[r].z : xv[r].w;
                            const ull xp = pack2(xe, xe);
                            acc0[r] = fma2(wv.x, xp, acc0[r]);
                            acc1[r] = fma2(wv.y, xp, acc1[r]);
                        }
                    }
                }
            }

            #pragma unroll
            for (int r = 0; r < 8; r++) {
                ull* dst = (ull*)&g_xproj[((size_t)s * 64 + rg * 8 + r) * 256 + 4 * jq];
                dst[0] = acc0[r];
                dst[1] = acc1[r];
            }
            __threadfence();
            __syncthreads();
            if (t == 0) st_release(&g_flag[s], 1);
        }
    }
}

// ---------------------------------------------------------------------------
extern "C" void kernel_launch(void* const* d_in, const int* in_sizes, int n_in,
                              void* d_out, int out_size)
{
    const float* sentence = (const float*)d_in[0];
    const float* h0       = (const float*)d_in[1];
    const float* W_ih     = (const float*)d_in[2];
    const float* W_hh     = (const float*)d_in[3];
    const float* bias     = (const float*)d_in[4];
    float* out = (float*)d_out;

    (void)in_sizes; (void)n_in; (void)out_size;

    zero_flags<<<(S_LEN + 511) / 512, 512>>>();

    // smem: scan sW 96KB + part 8KB + hbuf 2KB = 106 KB (worker: 96 KB)
    const int smem_bytes = (8 * K_SMEM * 64) * 16 + (8 * 128) * 8 + 256 * 8;
    cudaFuncSetAttribute(fused_kernel,
                         cudaFuncAttributeMaxDynamicSharedMemorySize,
                         smem_bytes);
    fused_kernel<<<B_SZ + NWORK, 512, smem_bytes>>>(
        sentence, W_ih, bias, W_hh, h0, out);
}